// round 3
// baseline (speedup 1.0000x reference)
#include <cuda_runtime.h>
#include <cstdint>

#define NB 32
#define C  128
#define H  56
#define W  56
#define HWsz (H*W)
#define NPIX (NB*H*W)          /* 100352 */
#define NELEM (NPIX*C)         /* 12845056 */
#define WELEM (C*C*9)          /* 147456 */

// -------- scratch (device globals; no allocations) --------
__device__ __align__(16) int8_t g_x_i8[NELEM];   // quantized input, NHWC, int in [-8,7]
__device__ __align__(16) int8_t g_a1[NELEM];     // quantized relu1 activations, NHWC, [0,15]
__device__ __align__(16) int8_t g_w1q[WELEM];    // [co][kh][kw][ci]
__device__ __align__(16) int8_t g_w2q[WELEM];
__device__ __align__(16) float  g_t[NELEM];      // conv1 out (NHWC), then conv2 out (NCHW)
__device__ unsigned g_max[8];                    // 0:max|x| 1:max|w1| 2:max|w2| 3:max relu1 4:max relu2
__device__ float g_A1[C], g_D1[C], g_A2[C], g_D2[C];

__global__ void k_init() { if (threadIdx.x < 8) g_max[threadIdx.x] = 0u; }

// -------- abs-max of x --------
__global__ void k_absmax_x(const float* __restrict__ p) {
    float m = 0.f;
    for (int i = blockIdx.x*blockDim.x + threadIdx.x; i < NELEM; i += gridDim.x*blockDim.x)
        m = fmaxf(m, fabsf(p[i]));
    #pragma unroll
    for (int off = 16; off; off >>= 1) m = fmaxf(m, __shfl_xor_sync(0xffffffffu, m, off));
    __shared__ float sm[8];
    int lane = threadIdx.x & 31, wid = threadIdx.x >> 5;
    if (lane == 0) sm[wid] = m;
    __syncthreads();
    if (threadIdx.x == 0) {
        float mm = sm[0];
        #pragma unroll
        for (int i = 1; i < 8; i++) mm = fmaxf(mm, sm[i]);
        atomicMax(&g_max[0], __float_as_uint(mm));
    }
}

// -------- abs-max of both weight tensors (slot 1 = w1, slot 2 = w2) --------
__global__ void k_absmax_w(const float* __restrict__ wA, const float* __restrict__ wB) {
    int which = blockIdx.y;                       // 0 -> w1, 1 -> w2
    const float* p = which ? wB : wA;
    float m = 0.f;
    for (int i = blockIdx.x*blockDim.x + threadIdx.x; i < WELEM; i += gridDim.x*blockDim.x)
        m = fmaxf(m, fabsf(p[i]));
    #pragma unroll
    for (int off = 16; off; off >>= 1) m = fmaxf(m, __shfl_xor_sync(0xffffffffu, m, off));
    __shared__ float sm[8];
    int lane = threadIdx.x & 31, wid = threadIdx.x >> 5;
    if (lane == 0) sm[wid] = m;
    __syncthreads();
    if (threadIdx.x == 0) {
        float mm = sm[0];
        #pragma unroll
        for (int i = 1; i < 8; i++) mm = fmaxf(mm, sm[i]);
        atomicMax(&g_max[which + 1], __float_as_uint(mm));
    }
}

// -------- quantize input NCHW float -> NHWC int8 [-8,7] --------
__global__ void k_quant_x(const float* __restrict__ x) {
    int pix = blockIdx.x*blockDim.x + threadIdx.x;
    if (pix >= NPIX) return;
    float s = fmaxf(__uint_as_float(g_max[0]) / 7.0f, 1e-8f);
    int n = pix / HWsz, hw = pix % HWsz;
    const float* xp = x + (size_t)n*C*HWsz + hw;
    char4* op = (char4*)(g_x_i8 + (size_t)pix*C);
    #pragma unroll 4
    for (int c4 = 0; c4 < C/4; c4++) {
        char4 q;
        float v;
        v = xp[(c4*4+0)*HWsz]; q.x = (signed char)fminf(fmaxf(rintf(v/s), -8.f), 7.f);
        v = xp[(c4*4+1)*HWsz]; q.y = (signed char)fminf(fmaxf(rintf(v/s), -8.f), 7.f);
        v = xp[(c4*4+2)*HWsz]; q.z = (signed char)fminf(fmaxf(rintf(v/s), -8.f), 7.f);
        v = xp[(c4*4+3)*HWsz]; q.w = (signed char)fminf(fmaxf(rintf(v/s), -8.f), 7.f);
        op[c4] = q;
    }
}

// -------- quantize BOTH weights OIHW float -> [co][kh][kw][ci] int8 [-8,7] --------
__global__ void k_quant_w(const float* __restrict__ wA, const float* __restrict__ wB) {
    int gi = blockIdx.x*blockDim.x + threadIdx.x;
    if (gi >= 2*WELEM) return;
    int which = gi >= WELEM;
    int i = which ? (gi - WELEM) : gi;
    const float* w = which ? wB : wA;
    float s = fmaxf(__uint_as_float(g_max[which ? 2 : 1]) / 7.0f, 1e-8f);
    int ci = i & (C-1);
    int kw = (i >> 7) % 3;
    int kh = ((i >> 7) / 3) % 3;
    int co = i / (9*C);
    float v = w[((size_t)(co*C + ci)*3 + kh)*3 + kw];
    signed char q = (signed char)fminf(fmaxf(rintf(v/s), -8.f), 7.f);
    if (which) g_w2q[i] = q; else g_w1q[i] = q;
}

// -------- fold bias quant + BN into per-channel A, D --------
__global__ void k_affine(const float* __restrict__ b, const float* __restrict__ g,
                         const float* __restrict__ be, const float* __restrict__ m,
                         const float* __restrict__ v,
                         int slot_in, float div_in, int slot_w, int which) {
    int c = threadIdx.x;
    if (c >= C) return;
    float si = fmaxf(__uint_as_float(g_max[slot_in]) / div_in, 1e-8f);
    float sw = fmaxf(__uint_as_float(g_max[slot_w]) / 7.0f, 1e-8f);
    float sb = si * sw;
    float qb = rintf(b[c] / sb);
    float inv = g[c] / sqrtf(v[c] + 1e-5f);
    float A  = sb * inv;
    float Dv = qb * sb * inv + be[c] - m[c] * inv;
    if (which == 1) { g_A1[c] = A; g_D1[c] = Dv; }
    else            { g_A2[c] = A; g_D2[c] = Dv; }
}

// -------- 3x3 conv, int8 dp4a, NHWC in, pad 1 --------
// block: 512 threads = 128 cout x 4 pixel-groups of 7; tile = 28 pixels of one row
template<int PASS>
__global__ void __launch_bounds__(512) k_conv() {
    constexpr int TW = 28, SMW = TW + 2;
    __shared__ __align__(16) int8_t stile[3*SMW*C];   // 11520 B
    const int8_t* __restrict__ in = (PASS == 1) ? g_x_i8 : g_a1;
    const int8_t* __restrict__ wq = (PASS == 1) ? g_w1q  : g_w2q;
    const float*  __restrict__ Ap = (PASS == 1) ? g_A1 : g_A2;
    const float*  __restrict__ Dp = (PASS == 1) ? g_D1 : g_D2;

    int n = blockIdx.z, h = blockIdx.y, w0 = blockIdx.x * TW;
    int tid = threadIdx.x;

    // cooperative smem fill: rows h-1..h+1, width w0-1..w0+28, all 128 cin (zero-padded)
    int* s32 = (int*)stile;
    for (int i = tid; i < 3*SMW*C/4; i += 512) {
        int c4 = i & 31;
        int pixloc = i >> 5;
        int wi = pixloc % SMW, ri = pixloc / SMW;
        int gh = h + ri - 1, gw = w0 + wi - 1;
        int val = 0;
        if ((unsigned)gh < (unsigned)H && (unsigned)gw < (unsigned)W)
            val = __ldg((const int*)in + (size_t)((n*H + gh)*W + gw)*(C/4) + c4);
        s32[i] = val;
    }
    __syncthreads();

    int co = tid & (C-1);
    int pg = tid >> 7;   // 0..3
    int acc[7] = {0,0,0,0,0,0,0};
    const int4* __restrict__ wb = (const int4*)(wq + (size_t)co*9*C);

    #pragma unroll
    for (int kh = 0; kh < 3; kh++) {
        const int4* srow = (const int4*)(stile + kh*SMW*C);
        #pragma unroll
        for (int c4 = 0; c4 < 8; c4++) {
            int4 iv[9];
            #pragma unroll
            for (int j = 0; j < 9; j++) iv[j] = srow[(pg*7 + j)*8 + c4];  // warp-broadcast
            #pragma unroll
            for (int kw = 0; kw < 3; kw++) {
                int4 wv = __ldg(&wb[(kh*3+kw)*8 + c4]);
                #pragma unroll
                for (int p = 0; p < 7; p++) {
                    int4 a = iv[p+kw];
                    acc[p] = __dp4a(a.x, wv.x, acc[p]);
                    acc[p] = __dp4a(a.y, wv.y, acc[p]);
                    acc[p] = __dp4a(a.z, wv.z, acc[p]);
                    acc[p] = __dp4a(a.w, wv.w, acc[p]);
                }
            }
        }
    }

    float a = Ap[co], d = Dp[co];
    float sid = 0.f;
    if (PASS == 2) sid = fmaxf(__uint_as_float(g_max[0]) / 7.0f, 1e-8f);
    float lmax = 0.f;
    int pixbase = (n*H + h)*W + w0 + pg*7;
    #pragma unroll
    for (int p = 0; p < 7; p++) {
        float v = (float)acc[p] * a + d;
        if (PASS == 2) v += sid * (float)__ldg(&g_x_i8[(size_t)(pixbase+p)*C + co]);
        lmax = fmaxf(lmax, v);
        if (PASS == 1)
            g_t[(size_t)(pixbase+p)*C + co] = v;                               // NHWC
        else
            g_t[((size_t)n*C + co)*HWsz + h*W + (w0 + pg*7 + p)] = v;          // NCHW
    }

    // block reduce relu-max, one atomic per block
    #pragma unroll
    for (int off = 16; off; off >>= 1) lmax = fmaxf(lmax, __shfl_xor_sync(0xffffffffu, lmax, off));
    __shared__ float smax[16];
    if ((tid & 31) == 0) smax[tid >> 5] = lmax;
    __syncthreads();
    if (tid == 0) {
        float mm = smax[0];
        #pragma unroll
        for (int i = 1; i < 16; i++) mm = fmaxf(mm, smax[i]);
        atomicMax(&g_max[(PASS == 1) ? 3 : 4], __float_as_uint(mm));
    }
}

// -------- QuantReLU of conv1 output -> uint4-as-int8 NHWC --------
__global__ void k_qrelu() {
    int i = blockIdx.x*blockDim.x + threadIdx.x;
    if (i >= NELEM/4) return;
    float s = fmaxf(__uint_as_float(g_max[3]) / 15.0f, 1e-8f);
    float4 v = ((const float4*)g_t)[i];
    char4 q;
    q.x = (signed char)fminf(fmaxf(rintf(fmaxf(v.x, 0.f)/s), 0.f), 15.f);
    q.y = (signed char)fminf(fmaxf(rintf(fmaxf(v.y, 0.f)/s), 0.f), 15.f);
    q.z = (signed char)fminf(fmaxf(rintf(fmaxf(v.z, 0.f)/s), 0.f), 15.f);
    q.w = (signed char)fminf(fmaxf(rintf(fmaxf(v.w, 0.f)/s), 0.f), 15.f);
    ((char4*)g_a1)[i] = q;
}

// -------- final QuantReLU (NCHW float -> NCHW float) --------
__global__ void k_final(float* __restrict__ out) {
    int i = blockIdx.x*blockDim.x + threadIdx.x;
    if (i >= NELEM/4) return;
    float s = fmaxf(__uint_as_float(g_max[4]) / 15.0f, 1e-8f);
    float4 v = ((const float4*)g_t)[i];
    float4 o;
    o.x = fminf(fmaxf(rintf(fmaxf(v.x, 0.f)/s), 0.f), 15.f) * s;
    o.y = fminf(fmaxf(rintf(fmaxf(v.y, 0.f)/s), 0.f), 15.f) * s;
    o.z = fminf(fmaxf(rintf(fmaxf(v.z, 0.f)/s), 0.f), 15.f) * s;
    o.w = fminf(fmaxf(rintf(fmaxf(v.w, 0.f)/s), 0.f), 15.f) * s;
    ((float4*)out)[i] = o;
}

extern "C" void kernel_launch(void* const* d_in, const int* in_sizes, int n_in,
                              void* d_out, int out_size) {
    const float* x   = (const float*)d_in[0];
    const float* w1  = (const float*)d_in[1];
    const float* b1  = (const float*)d_in[2];
    const float* g1  = (const float*)d_in[3];
    const float* be1 = (const float*)d_in[4];
    const float* m1  = (const float*)d_in[5];
    const float* v1  = (const float*)d_in[6];
    const float* w2  = (const float*)d_in[7];
    const float* b2  = (const float*)d_in[8];
    const float* g2  = (const float*)d_in[9];
    const float* be2 = (const float*)d_in[10];
    const float* m2  = (const float*)d_in[11];
    const float* v2  = (const float*)d_in[12];
    float* out = (float*)d_out;

    k_init<<<1, 32>>>();
    k_absmax_x<<<1024, 256>>>(x);
    k_absmax_w<<<dim3(64, 2), 256>>>(w1, w2);
    k_quant_x<<<(NPIX + 255)/256, 256>>>(x);
    k_quant_w<<<(2*WELEM + 255)/256, 256>>>(w1, w2);
    k_affine<<<1, 128>>>(b1, g1, be1, m1, v1, /*slot_in*/0, 7.0f, /*slot_w*/1, 1);

    dim3 cg(W/28, H, NB);   // 2 x 56 x 32
    k_conv<1><<<cg, 512>>>();

    k_affine<<<1, 128>>>(b2, g2, be2, m2, v2, /*slot_in*/3, 15.0f, /*slot_w*/2, 2);
    k_qrelu<<<(NELEM/4 + 255)/256, 256>>>();

    k_conv<2><<<cg, 512>>>();
    k_final<<<(NELEM/4 + 255)/256, 256>>>(out);
}

// round 5
// speedup vs baseline: 1.7671x; 1.7671x over previous
#include <cuda_runtime.h>
#include <cstdint>

#define NB 32
#define C  128
#define H  56
#define W  56
#define HWsz (H*W)
#define NPIX (NB*H*W)          /* 100352 */
#define NELEM (NPIX*C)         /* 12845056 */
#define WELEM (C*C*9)          /* 147456 */

// -------- scratch (device globals; no allocations) --------
__device__ __align__(16) int8_t g_x_i8[NELEM];   // quantized input, NHWC, [-8,7]
__device__ __align__(16) int8_t g_a1[NELEM];     // quantized relu1 acts, NHWC, [0,15]
__device__ __align__(16) int8_t g_w1q[WELEM];    // [co][kh][kw][ci]
__device__ __align__(16) int8_t g_w2q[WELEM];
__device__ __align__(16) float  g_t[NELEM];      // conv outputs, NHWC (both passes)
__device__ unsigned g_max[8];                    // 0:|x| 1:|w1| 2:|w2| 3:relu1 4:relu2
__device__ float g_A1[C], g_D1[C], g_A2[C], g_D2[C];

__global__ void k_init() { if (threadIdx.x < 8) g_max[threadIdx.x] = 0u; }

// -------- abs-max of x --------
__global__ void k_absmax_x(const float* __restrict__ p) {
    float m = 0.f;
    for (int i = blockIdx.x*blockDim.x + threadIdx.x; i < NELEM; i += gridDim.x*blockDim.x)
        m = fmaxf(m, fabsf(p[i]));
    #pragma unroll
    for (int off = 16; off; off >>= 1) m = fmaxf(m, __shfl_xor_sync(0xffffffffu, m, off));
    __shared__ float sm[8];
    int lane = threadIdx.x & 31, wid = threadIdx.x >> 5;
    if (lane == 0) sm[wid] = m;
    __syncthreads();
    if (threadIdx.x == 0) {
        float mm = sm[0];
        #pragma unroll
        for (int i = 1; i < 8; i++) mm = fmaxf(mm, sm[i]);
        atomicMax(&g_max[0], __float_as_uint(mm));
    }
}

// -------- abs-max of both weight tensors --------
__global__ void k_absmax_w(const float* __restrict__ wA, const float* __restrict__ wB) {
    int which = blockIdx.y;
    const float* p = which ? wB : wA;
    float m = 0.f;
    for (int i = blockIdx.x*blockDim.x + threadIdx.x; i < WELEM; i += gridDim.x*blockDim.x)
        m = fmaxf(m, fabsf(p[i]));
    #pragma unroll
    for (int off = 16; off; off >>= 1) m = fmaxf(m, __shfl_xor_sync(0xffffffffu, m, off));
    __shared__ float sm[8];
    int lane = threadIdx.x & 31, wid = threadIdx.x >> 5;
    if (lane == 0) sm[wid] = m;
    __syncthreads();
    if (threadIdx.x == 0) {
        float mm = sm[0];
        #pragma unroll
        for (int i = 1; i < 8; i++) mm = fmaxf(mm, sm[i]);
        atomicMax(&g_max[which + 1], __float_as_uint(mm));
    }
}

// -------- quantize input: NCHW float -> NHWC int8, smem-tiled transpose --------
__global__ void __launch_bounds__(256) k_quant_x(const float* __restrict__ x) {
    __shared__ int8_t tile[32 * 144];
    int n = blockIdx.y, hw0 = blockIdx.x * 32;
    float s = fmaxf(__uint_as_float(g_max[0]) / 7.0f, 1e-8f);
    int lane = threadIdx.x & 31, ty = threadIdx.x >> 5;
    #pragma unroll
    for (int it = 0; it < 16; it++) {
        int c = ty + 8 * it;
        float v = x[((size_t)n*C + c)*HWsz + hw0 + lane];
        tile[lane * 144 + c] = (int8_t)fminf(fmaxf(rintf(v/s), -8.f), 7.f);
    }
    __syncthreads();
    int p = threadIdx.x >> 3, w16 = threadIdx.x & 7;
    int4 v = *(const int4*)(tile + p * 144 + w16 * 16);
    *(int4*)(g_x_i8 + (size_t)(n*HWsz + hw0 + p)*C + w16*16) = v;
}

// -------- quantize BOTH weights OIHW float -> [co][kh][kw][ci] int8 --------
__global__ void k_quant_w(const float* __restrict__ wA, const float* __restrict__ wB) {
    int gi = blockIdx.x*blockDim.x + threadIdx.x;
    if (gi >= 2*WELEM) return;
    int which = gi >= WELEM;
    int i = which ? (gi - WELEM) : gi;
    const float* w = which ? wB : wA;
    float s = fmaxf(__uint_as_float(g_max[which ? 2 : 1]) / 7.0f, 1e-8f);
    int ci = i & (C-1);
    int kw = (i >> 7) % 3;
    int kh = ((i >> 7) / 3) % 3;
    int co = i / (9*C);
    float v = w[((size_t)(co*C + ci)*3 + kh)*3 + kw];
    signed char q = (signed char)fminf(fmaxf(rintf(v/s), -8.f), 7.f);
    if (which) g_w2q[i] = q; else g_w1q[i] = q;
}

// -------- fold bias quant + BN into per-channel A, D --------
__global__ void k_affine(const float* __restrict__ b, const float* __restrict__ g,
                         const float* __restrict__ be, const float* __restrict__ m,
                         const float* __restrict__ v,
                         int slot_in, float div_in, int slot_w, int which) {
    int c = threadIdx.x;
    if (c >= C) return;
    float si = fmaxf(__uint_as_float(g_max[slot_in]) / div_in, 1e-8f);
    float sw = fmaxf(__uint_as_float(g_max[slot_w]) / 7.0f, 1e-8f);
    float sb = si * sw;
    float qb = rintf(b[c] / sb);
    float inv = g[c] / sqrtf(v[c] + 1e-5f);
    float A  = sb * inv;
    float Dv = qb * sb * inv + be[c] - m[c] * inv;
    if (which == 1) { g_A1[c] = A; g_D1[c] = Dv; }
    else            { g_A2[c] = A; g_D2[c] = Dv; }
}

// ================= int8 tensor-core conv (mma.sync m16n8k32) =================
// Block = 2 image rows (112 px -> M=128) x 128 couts. 256 thr = 8 warps.
// Warp w: pixels [w*16, w*16+16), all 128 couts (16 n8-tiles).
// K = 9 taps x 128 cin (4 k32 steps each). Weights + haloed act slab in SMEM.

#define SW_BYTES (9*C*C)          /* 147456 */
#define SA_BYTES (4*58*C)         /* 29696  */
#define SMEM_CONV (SW_BYTES + SA_BYTES)

__device__ __forceinline__ uint32_t s2u(const void* p) {
    return (uint32_t)__cvta_generic_to_shared(p);
}
#define LDSM4(r0,r1,r2,r3,addr) \
    asm volatile("ldmatrix.sync.aligned.m8n8.x4.shared.b16 {%0,%1,%2,%3}, [%4];" \
        : "=r"(r0),"=r"(r1),"=r"(r2),"=r"(r3) : "r"(addr))
#define MMA16832(c,a0,a1,a2,a3,b0,b1) \
    asm volatile("mma.sync.aligned.m16n8k32.row.col.s32.s8.s8.s32 " \
        "{%0,%1,%2,%3},{%4,%5,%6,%7},{%8,%9},{%0,%1,%2,%3};" \
        : "+r"((c)[0]),"+r"((c)[1]),"+r"((c)[2]),"+r"((c)[3]) \
        : "r"(a0),"r"(a1),"r"(a2),"r"(a3),"r"(b0),"r"(b1))

template<int PASS>
__global__ void __launch_bounds__(256) k_conv() {
    extern __shared__ __align__(16) int8_t smc[];
    int8_t* sw = smc;                 // [co][tap][ci] linear copy of weights
    int8_t* sa = smc + SW_BYTES;      // [4 rows][58 cols][128 ci], zero halo
    const int8_t* __restrict__ in = (PASS == 1) ? g_x_i8 : g_a1;
    const int8_t* __restrict__ wq = (PASS == 1) ? g_w1q  : g_w2q;
    const float*  __restrict__ Ap = (PASS == 1) ? g_A1 : g_A2;
    const float*  __restrict__ Dp = (PASS == 1) ? g_D1 : g_D2;

    int n = blockIdx.y, h2 = blockIdx.x;        // output rows 2*h2, 2*h2+1
    int tid = threadIdx.x;

    // fill weights: straight 147456B copy (coalesced int4)
    {
        const int4* src = (const int4*)wq;
        int4* dst = (int4*)sw;
        #pragma unroll 4
        for (int i = tid; i < SW_BYTES/16; i += 256) dst[i] = src[i];
    }
    // fill act slab: input rows 2*h2-1 .. 2*h2+2, cols -1..56, zero-padded
    {
        int4* dst = (int4*)sa;
        for (int i = tid; i < SA_BYTES/16; i += 256) {
            int c16 = i & 7;
            int rowi = i >> 3;                  // 0..231
            int ir = rowi / 58, col = rowi % 58;
            int hh = h2*2 + ir - 1, ww = col - 1;
            int4 v = make_int4(0,0,0,0);
            if ((unsigned)hh < (unsigned)H && (unsigned)ww < (unsigned)W)
                v = __ldg((const int4*)(in + (size_t)((n*H + hh)*W + ww)*C) + c16);
            dst[i] = v;
        }
    }
    __syncthreads();

    int warp = tid >> 5, L = tid & 31;

    // A fragment lane address: lanes 0-7 rows0-7/k0, 8-15 rows8-15/k0,
    // 16-23 rows0-7/k16, 24-31 rows8-15/k16
    int apix = warp*16 + (L & 15);
    int ph = apix / 56, pw = apix % 56;
    if (apix >= 112) { ph = 0; pw = 0; }        // dummy rows, results discarded
    uint32_t aBase = s2u(sa) + (uint32_t)((ph*58 + pw)*C) + ((L >> 4) << 4);

    // B fragment lane address (two n8 tiles per x4):
    // co = (L%8) + 8*(L/16), k-half = (L/8)&1 ; row stride = 9*128 = 1152
    int coL = (L & 7) + ((L >> 4) << 3);
    uint32_t bBase = s2u(sw) + (uint32_t)(coL * (9*C)) + (((L >> 3) & 1) << 4);

    int acc[16][4];
    #pragma unroll
    for (int t = 0; t < 16; t++) { acc[t][0]=0; acc[t][1]=0; acc[t][2]=0; acc[t][3]=0; }

    for (int tap = 0; tap < 9; tap++) {
        int kh = tap / 3, kw = tap - 3*kh;
        uint32_t aT = aBase + (uint32_t)((kh*58 + kw)*C);
        uint32_t bT = bBase + (uint32_t)(tap*C);
        #pragma unroll
        for (int ks = 0; ks < 4; ks++) {
            uint32_t a0,a1,a2,a3;
            LDSM4(a0,a1,a2,a3, aT + ks*32);
            uint32_t bk = bT + ks*32;
            #pragma unroll
            for (int g = 0; g < 8; g++) {
                uint32_t b0,b1,b2,b3;
                LDSM4(b0,b1,b2,b3, bk + (uint32_t)(g * 16 * (9*C)));
                MMA16832(acc[2*g  ], a0,a1,a2,a3, b0,b1);
                MMA16832(acc[2*g+1], a0,a1,a2,a3, b2,b3);
            }
        }
    }

    // epilogue: v = acc*A[co] + D[co] (+ residual), relu-max, NHWC float store
    float sid = 0.f;
    if (PASS == 2) sid = fmaxf(__uint_as_float(g_max[0]) / 7.0f, 1e-8f);
    int row0 = warp*16 + (L >> 2);
    int q2 = (L & 3) * 2;
    float lmax = 0.f;
    #pragma unroll
    for (int t = 0; t < 16; t++) {
        int co = t*8 + q2;
        float A0 = Ap[co], A1 = Ap[co+1], D0 = Dp[co], D1 = Dp[co+1];
        #pragma unroll
        for (int half = 0; half < 2; half++) {
            int pix = row0 + 8*half;
            if (pix < 112) {
                int gp = (n*H + h2*2 + pix/56)*W + pix%56;
                float v0 = (float)acc[t][2*half  ] * A0 + D0;
                float v1 = (float)acc[t][2*half+1] * A1 + D1;
                if (PASS == 2) {
                    char2 rr = *(const char2*)&g_x_i8[(size_t)gp*C + co];
                    v0 += sid * (float)rr.x;
                    v1 += sid * (float)rr.y;
                }
                lmax = fmaxf(lmax, fmaxf(v0, v1));
                float2 o; o.x = v0; o.y = v1;
                *(float2*)&g_t[(size_t)gp*C + co] = o;
            }
        }
    }

    #pragma unroll
    for (int off = 16; off; off >>= 1) lmax = fmaxf(lmax, __shfl_xor_sync(0xffffffffu, lmax, off));
    __shared__ float smax[8];
    if (L == 0) smax[warp] = lmax;
    __syncthreads();
    if (tid == 0) {
        float mm = smax[0];
        #pragma unroll
        for (int i = 1; i < 8; i++) mm = fmaxf(mm, smax[i]);
        atomicMax(&g_max[(PASS == 1) ? 3 : 4], __float_as_uint(mm));
    }
}

// -------- QuantReLU of conv1 output -> uint4-as-int8 NHWC --------
__global__ void k_qrelu() {
    int i = blockIdx.x*blockDim.x + threadIdx.x;
    if (i >= NELEM/4) return;
    float s = fmaxf(__uint_as_float(g_max[3]) / 15.0f, 1e-8f);
    float4 v = ((const float4*)g_t)[i];
    char4 q;
    q.x = (signed char)fminf(fmaxf(rintf(fmaxf(v.x, 0.f)/s), 0.f), 15.f);
    q.y = (signed char)fminf(fmaxf(rintf(fmaxf(v.y, 0.f)/s), 0.f), 15.f);
    q.z = (signed char)fminf(fmaxf(rintf(fmaxf(v.z, 0.f)/s), 0.f), 15.f);
    q.w = (signed char)fminf(fmaxf(rintf(fmaxf(v.w, 0.f)/s), 0.f), 15.f);
    ((char4*)g_a1)[i] = q;
}

// -------- final QuantReLU + NHWC->NCHW transpose, smem-tiled --------
__global__ void __launch_bounds__(256) k_final(float* __restrict__ out) {
    __shared__ float tile[32][33];
    int n = blockIdx.z, c0 = blockIdx.y * 32, hw0 = blockIdx.x * 32;
    float s = fmaxf(__uint_as_float(g_max[4]) / 15.0f, 1e-8f);
    int lane = threadIdx.x & 31, ty = threadIdx.x >> 5;
    #pragma unroll
    for (int it = 0; it < 4; it++) {
        int p = ty + 8 * it;
        float v = g_t[(size_t)(n*HWsz + hw0 + p)*C + c0 + lane];
        tile[lane][p] = fminf(fmaxf(rintf(fmaxf(v, 0.f)/s), 0.f), 15.f) * s;
    }
    __syncthreads();
    #pragma unroll
    for (int it = 0; it < 4; it++) {
        int c = ty + 8 * it;
        out[((size_t)n*C + c0 + c)*HWsz + hw0 + lane] = tile[c][lane];
    }
}

extern "C" void kernel_launch(void* const* d_in, const int* in_sizes, int n_in,
                              void* d_out, int out_size) {
    const float* x   = (const float*)d_in[0];
    const float* w1  = (const float*)d_in[1];
    const float* b1  = (const float*)d_in[2];
    const float* g1  = (const float*)d_in[3];
    const float* be1 = (const float*)d_in[4];
    const float* m1  = (const float*)d_in[5];
    const float* v1  = (const float*)d_in[6];
    const float* w2  = (const float*)d_in[7];
    const float* b2  = (const float*)d_in[8];
    const float* g2  = (const float*)d_in[9];
    const float* be2 = (const float*)d_in[10];
    const float* m2  = (const float*)d_in[11];
    const float* v2  = (const float*)d_in[12];
    float* out = (float*)d_out;

    cudaFuncSetAttribute(k_conv<1>, cudaFuncAttributeMaxDynamicSharedMemorySize, SMEM_CONV);
    cudaFuncSetAttribute(k_conv<2>, cudaFuncAttributeMaxDynamicSharedMemorySize, SMEM_CONV);

    k_init<<<1, 32>>>();
    k_absmax_x<<<1024, 256>>>(x);
    k_absmax_w<<<dim3(64, 2), 256>>>(w1, w2);
    k_quant_x<<<dim3(HWsz/32, NB), 256>>>(x);
    k_quant_w<<<(2*WELEM + 255)/256, 256>>>(w1, w2);
    k_affine<<<1, 128>>>(b1, g1, be1, m1, v1, 0, 7.0f, 1, 1);

    dim3 cg(H/2, NB);   // 28 x 32
    k_conv<1><<<cg, 256, SMEM_CONV>>>();

    k_affine<<<1, 128>>>(b2, g2, be2, m2, v2, 3, 15.0f, 2, 2);
    k_qrelu<<<(NELEM/4 + 255)/256, 256>>>();

    k_conv<2><<<cg, 256, SMEM_CONV>>>();
    k_final<<<dim3(HWsz/32, C/32, NB), 256>>>(out);
}

// round 12
// speedup vs baseline: 1.9140x; 1.0831x over previous
#include <cuda_runtime.h>
#include <cstdint>

#define NB 32
#define C  128
#define H  56
#define W  56
#define HWsz (H*W)
#define NPIX (NB*H*W)          /* 100352 */
#define NELEM (NPIX*C)         /* 12845056 */
#define WELEM (C*C*9)          /* 147456 */

// -------- scratch (device globals; no allocations) --------
__device__ __align__(16) int8_t g_x_i8[NELEM];   // quantized input, NHWC, [-8,7]
__device__ __align__(16) int8_t g_a1[NELEM];     // quantized relu1 acts, NHWC, [0,15]
__device__ __align__(16) int8_t g_w1q[WELEM];    // [co][kh][kw][ci]
__device__ __align__(16) int8_t g_w2q[WELEM];
__device__ __align__(16) float  g_t[NELEM];      // conv outputs, NHWC (both passes)
__device__ unsigned g_max[8];                    // 0:|x| 1:|w1| 2:|w2| 3:relu1 4:relu2
__device__ float g_A1[C], g_D1[C], g_A2[C], g_D2[C];

__global__ void k_init() { if (threadIdx.x < 8) g_max[threadIdx.x] = 0u; }

// -------- abs-max of x --------
__global__ void k_absmax_x(const float* __restrict__ p) {
    float m = 0.f;
    for (int i = blockIdx.x*blockDim.x + threadIdx.x; i < NELEM; i += gridDim.x*blockDim.x)
        m = fmaxf(m, fabsf(p[i]));
    #pragma unroll
    for (int off = 16; off; off >>= 1) m = fmaxf(m, __shfl_xor_sync(0xffffffffu, m, off));
    __shared__ float sm[8];
    int lane = threadIdx.x & 31, wid = threadIdx.x >> 5;
    if (lane == 0) sm[wid] = m;
    __syncthreads();
    if (threadIdx.x == 0) {
        float mm = sm[0];
        #pragma unroll
        for (int i = 1; i < 8; i++) mm = fmaxf(mm, sm[i]);
        atomicMax(&g_max[0], __float_as_uint(mm));
    }
}

// -------- abs-max of both weight tensors --------
__global__ void k_absmax_w(const float* __restrict__ wA, const float* __restrict__ wB) {
    int which = blockIdx.y;
    const float* p = which ? wB : wA;
    float m = 0.f;
    for (int i = blockIdx.x*blockDim.x + threadIdx.x; i < WELEM; i += gridDim.x*blockDim.x)
        m = fmaxf(m, fabsf(p[i]));
    #pragma unroll
    for (int off = 16; off; off >>= 1) m = fmaxf(m, __shfl_xor_sync(0xffffffffu, m, off));
    __shared__ float sm[8];
    int lane = threadIdx.x & 31, wid = threadIdx.x >> 5;
    if (lane == 0) sm[wid] = m;
    __syncthreads();
    if (threadIdx.x == 0) {
        float mm = sm[0];
        #pragma unroll
        for (int i = 1; i < 8; i++) mm = fmaxf(mm, sm[i]);
        atomicMax(&g_max[which + 1], __float_as_uint(mm));
    }
}

// -------- quantize input: NCHW float -> NHWC int8, smem-tiled transpose --------
__global__ void __launch_bounds__(256) k_quant_x(const float* __restrict__ x) {
    __shared__ int8_t tile[32 * 144];
    int n = blockIdx.y, hw0 = blockIdx.x * 32;
    float s = fmaxf(__uint_as_float(g_max[0]) / 7.0f, 1e-8f);
    int lane = threadIdx.x & 31, ty = threadIdx.x >> 5;
    #pragma unroll
    for (int it = 0; it < 16; it++) {
        int c = ty + 8 * it;
        float v = x[((size_t)n*C + c)*HWsz + hw0 + lane];
        tile[lane * 144 + c] = (int8_t)fminf(fmaxf(rintf(v/s), -8.f), 7.f);
    }
    __syncthreads();
    int p = threadIdx.x >> 3, w16 = threadIdx.x & 7;
    int4 v = *(const int4*)(tile + p * 144 + w16 * 16);
    *(int4*)(g_x_i8 + (size_t)(n*HWsz + hw0 + p)*C + w16*16) = v;
}

// -------- quantize BOTH weights OIHW float -> [co][kh][kw][ci] int8 --------
__global__ void k_quant_w(const float* __restrict__ wA, const float* __restrict__ wB) {
    int gi = blockIdx.x*blockDim.x + threadIdx.x;
    if (gi >= 2*WELEM) return;
    int which = gi >= WELEM;
    int i = which ? (gi - WELEM) : gi;
    const float* w = which ? wB : wA;
    float s = fmaxf(__uint_as_float(g_max[which ? 2 : 1]) / 7.0f, 1e-8f);
    int ci = i & (C-1);
    int kw = (i >> 7) % 3;
    int kh = ((i >> 7) / 3) % 3;
    int co = i / (9*C);
    float v = w[((size_t)(co*C + ci)*3 + kh)*3 + kw];
    signed char q = (signed char)fminf(fmaxf(rintf(v/s), -8.f), 7.f);
    if (which) g_w2q[i] = q; else g_w1q[i] = q;
}

// -------- fold bias quant + BN into per-channel A, D --------
__global__ void k_affine(const float* __restrict__ b, const float* __restrict__ g,
                         const float* __restrict__ be, const float* __restrict__ m,
                         const float* __restrict__ v,
                         int slot_in, float div_in, int slot_w, int which) {
    int c = threadIdx.x;
    if (c >= C) return;
    float si = fmaxf(__uint_as_float(g_max[slot_in]) / div_in, 1e-8f);
    float sw = fmaxf(__uint_as_float(g_max[slot_w]) / 7.0f, 1e-8f);
    float sb = si * sw;
    float qb = rintf(b[c] / sb);
    float inv = g[c] / sqrtf(v[c] + 1e-5f);
    float A  = sb * inv;
    float Dv = qb * sb * inv + be[c] - m[c] * inv;
    if (which == 1) { g_A1[c] = A; g_D1[c] = Dv; }
    else            { g_A2[c] = A; g_D2[c] = Dv; }
}

// ================= int8 tensor-core conv (mma.sync m16n8k32) =================
// Block = 2 image rows (112 px -> M=128) x 128 couts. 256 thr = 8 warps.
// SMEM is XOR-swizzled: 16B chunk c within each 128B row stored at c ^ (row&7),
// making every ldmatrix phase (8 rows, same chunk) bank-conflict-free.

#define SW_BYTES (9*C*C)          /* 147456 */
#define SA_BYTES (4*58*C)         /* 29696  */
#define SMEM_CONV (SW_BYTES + SA_BYTES)

__device__ __forceinline__ uint32_t s2u(const void* p) {
    return (uint32_t)__cvta_generic_to_shared(p);
}
#define LDSM4(r0,r1,r2,r3,addr) \
    asm volatile("ldmatrix.sync.aligned.m8n8.x4.shared.b16 {%0,%1,%2,%3}, [%4];" \
        : "=r"(r0),"=r"(r1),"=r"(r2),"=r"(r3) : "r"(addr))
#define MMA16832(c,a0,a1,a2,a3,b0,b1) \
    asm volatile("mma.sync.aligned.m16n8k32.row.col.s32.s8.s8.s32 " \
        "{%0,%1,%2,%3},{%4,%5,%6,%7},{%8,%9},{%0,%1,%2,%3};" \
        : "+r"((c)[0]),"+r"((c)[1]),"+r"((c)[2]),"+r"((c)[3]) \
        : "r"(a0),"r"(a1),"r"(a2),"r"(a3),"r"(b0),"r"(b1))

template<int PASS>
__global__ void __launch_bounds__(256) k_conv() {
    extern __shared__ __align__(16) int8_t smc[];
    int8_t* sw = smc;                 // weights [co][tap][ci], swizzled
    int8_t* sa = smc + SW_BYTES;      // act slab [4 rows][58 cols][128 ci], swizzled
    const int8_t* __restrict__ in = (PASS == 1) ? g_x_i8 : g_a1;
    const int8_t* __restrict__ wq = (PASS == 1) ? g_w1q  : g_w2q;
    const float*  __restrict__ Ap = (PASS == 1) ? g_A1 : g_A2;
    const float*  __restrict__ Dp = (PASS == 1) ? g_D1 : g_D2;

    int n = blockIdx.y, h2 = blockIdx.x;        // output rows 2*h2, 2*h2+1
    int tid = threadIdx.x;

    // fill weights (coalesced read; dest chunk swizzled by co&7)
    {
        const int4* src = (const int4*)wq;
        int4* dst = (int4*)sw;
        #pragma unroll 4
        for (int i = tid; i < SW_BYTES/16; i += 256) {
            int co = i / 72;                       // 72 chunks (9*128B) per cout
            dst[(i & ~7) | ((i ^ co) & 7)] = src[i];
        }
    }
    // fill act slab (dest chunk swizzled by slab-pixel-row &7)
    {
        int4* dst = (int4*)sa;
        for (int i = tid; i < SA_BYTES/16; i += 256) {
            int rowi = i >> 3;                  // slab pixel index 0..231
            int ir = rowi / 58, col = rowi % 58;
            int hh = h2*2 + ir - 1, ww = col - 1;
            int4 v = make_int4(0,0,0,0);
            if ((unsigned)hh < (unsigned)H && (unsigned)ww < (unsigned)W)
                v = __ldg((const int4*)(in + (size_t)((n*H + hh)*W + ww)*C) + (i & 7));
            dst[(i & ~7) | ((i ^ rowi) & 7)] = v;
        }
    }
    __syncthreads();

    int warp = tid >> 5, L = tid & 31;

    // A fragment lane geometry
    int apix = warp*16 + (L & 15);
    int ph = apix / 56, pw = apix % 56;
    if (apix >= 112) { ph = 0; pw = 0; }        // dummy rows, results discarded
    int sBase = ph*58 + pw;                     // slab pixel index (before tap offset)
    int hk = L >> 4;                            // 0/1: k 0-15 vs 16-31 half
    uint32_t saU = s2u(sa);

    // B fragment lane geometry
    int coL = (L & 7) + ((L >> 4) << 3);
    int hkb = (L >> 3) & 1;
    int sxb = L & 7;                            // co&7, invariant over g (g*16)
    uint32_t bRow = s2u(sw) + (uint32_t)(coL * (9*C));

    int acc[16][4];
    #pragma unroll
    for (int t = 0; t < 16; t++) { acc[t][0]=0; acc[t][1]=0; acc[t][2]=0; acc[t][3]=0; }

    for (int tap = 0; tap < 9; tap++) {
        int kh = tap / 3, kw = tap - 3*kh;
        int s = sBase + kh*58 + kw;             // slab pixel row for this tap
        uint32_t aRow = saU + (uint32_t)(s * C);
        int sx = s & 7;
        uint32_t bT = bRow + (uint32_t)(tap*C);
        #pragma unroll
        for (int ks = 0; ks < 4; ks++) {
            uint32_t a0,a1,a2,a3;
            LDSM4(a0,a1,a2,a3, aRow + (uint32_t)(((2*ks + hk) ^ sx) << 4));
            uint32_t bOff = (uint32_t)(((2*ks + hkb) ^ sxb) << 4);
            #pragma unroll
            for (int g = 0; g < 8; g++) {
                uint32_t b0,b1,b2,b3;
                LDSM4(b0,b1,b2,b3, bT + (uint32_t)(g * 16 * (9*C)) + bOff);
                MMA16832(acc[2*g  ], a0,a1,a2,a3, b0,b1);
                MMA16832(acc[2*g+1], a0,a1,a2,a3, b2,b3);
            }
        }
    }

    // epilogue: v = acc*A[co] + D[co] (+ residual), relu-max, NHWC float store
    float sid = 0.f;
    if (PASS == 2) sid = fmaxf(__uint_as_float(g_max[0]) / 7.0f, 1e-8f);
    int row0 = warp*16 + (L >> 2);
    int q2 = (L & 3) * 2;
    float lmax = 0.f;
    #pragma unroll
    for (int t = 0; t < 16; t++) {
        int co = t*8 + q2;
        float A0 = Ap[co], A1 = Ap[co+1], D0 = Dp[co], D1 = Dp[co+1];
        #pragma unroll
        for (int half = 0; half < 2; half++) {
            int pix = row0 + 8*half;
            if (pix < 112) {
                int gp = (n*H + h2*2 + pix/56)*W + pix%56;
                float v0 = (float)acc[t][2*half  ] * A0 + D0;
                float v1 = (float)acc[t][2*half+1] * A1 + D1;
                if (PASS == 2) {
                    char2 rr = *(const char2*)&g_x_i8[(size_t)gp*C + co];
                    v0 += sid * (float)rr.x;
                    v1 += sid * (float)rr.y;
                }
                lmax = fmaxf(lmax, fmaxf(v0, v1));
                float2 o; o.x = v0; o.y = v1;
                *(float2*)&g_t[(size_t)gp*C + co] = o;
            }
        }
    }

    #pragma unroll
    for (int off = 16; off; off >>= 1) lmax = fmaxf(lmax, __shfl_xor_sync(0xffffffffu, lmax, off));
    __shared__ float smax[8];
    if (L == 0) smax[warp] = lmax;
    __syncthreads();
    if (tid == 0) {
        float mm = smax[0];
        #pragma unroll
        for (int i = 1; i < 8; i++) mm = fmaxf(mm, smax[i]);
        atomicMax(&g_max[(PASS == 1) ? 3 : 4], __float_as_uint(mm));
    }
}

// -------- QuantReLU of conv1 output -> uint4-as-int8 NHWC --------
__global__ void k_qrelu() {
    int i = blockIdx.x*blockDim.x + threadIdx.x;
    if (i >= NELEM/4) return;
    float s = fmaxf(__uint_as_float(g_max[3]) / 15.0f, 1e-8f);
    float4 v = ((const float4*)g_t)[i];
    char4 q;
    q.x = (signed char)fminf(fmaxf(rintf(fmaxf(v.x, 0.f)/s), 0.f), 15.f);
    q.y = (signed char)fminf(fmaxf(rintf(fmaxf(v.y, 0.f)/s), 0.f), 15.f);
    q.z = (signed char)fminf(fmaxf(rintf(fmaxf(v.z, 0.f)/s), 0.f), 15.f);
    q.w = (signed char)fminf(fmaxf(rintf(fmaxf(v.w, 0.f)/s), 0.f), 15.f);
    ((char4*)g_a1)[i] = q;
}

// -------- final QuantReLU + NHWC->NCHW transpose, smem-tiled --------
__global__ void __launch_bounds__(256) k_final(float* __restrict__ out) {
    __shared__ float tile[32][33];
    int n = blockIdx.z, c0 = blockIdx.y * 32, hw0 = blockIdx.x * 32;
    float s = fmaxf(__uint_as_float(g_max[4]) / 15.0f, 1e-8f);
    int lane = threadIdx.x & 31, ty = threadIdx.x >> 5;
    #pragma unroll
    for (int it = 0; it < 4; it++) {
        int p = ty + 8 * it;
        float v = g_t[(size_t)(n*HWsz + hw0 + p)*C + c0 + lane];
        tile[lane][p] = fminf(fmaxf(rintf(fmaxf(v, 0.f)/s), 0.f), 15.f) * s;
    }
    __syncthreads();
    #pragma unroll
    for (int it = 0; it < 4; it++) {
        int c = ty + 8 * it;
        out[((size_t)n*C + c0 + c)*HWsz + hw0 + lane] = tile[c][lane];
    }
}

extern "C" void kernel_launch(void* const* d_in, const int* in_sizes, int n_in,
                              void* d_out, int out_size) {
    const float* x   = (const float*)d_in[0];
    const float* w1  = (const float*)d_in[1];
    const float* b1  = (const float*)d_in[2];
    const float* g1  = (const float*)d_in[3];
    const float* be1 = (const float*)d_in[4];
    const float* m1  = (const float*)d_in[5];
    const float* v1  = (const float*)d_in[6];
    const float* w2  = (const float*)d_in[7];
    const float* b2  = (const float*)d_in[8];
    const float* g2  = (const float*)d_in[9];
    const float* be2 = (const float*)d_in[10];
    const float* m2  = (const float*)d_in[11];
    const float* v2  = (const float*)d_in[12];
    float* out = (float*)d_out;

    cudaFuncSetAttribute(k_conv<1>, cudaFuncAttributeMaxDynamicSharedMemorySize, SMEM_CONV);
    cudaFuncSetAttribute(k_conv<2>, cudaFuncAttributeMaxDynamicSharedMemorySize, SMEM_CONV);

    k_init<<<1, 32>>>();
    k_absmax_x<<<1024, 256>>>(x);
    k_absmax_w<<<dim3(64, 2), 256>>>(w1, w2);
    k_quant_x<<<dim3(HWsz/32, NB), 256>>>(x);
    k_quant_w<<<(2*WELEM + 255)/256, 256>>>(w1, w2);
    k_affine<<<1, 128>>>(b1, g1, be1, m1, v1, 0, 7.0f, 1, 1);

    dim3 cg(H/2, NB);   // 28 x 32
    k_conv<1><<<cg, 256, SMEM_CONV>>>();

    k_affine<<<1, 128>>>(b2, g2, be2, m2, v2, 3, 15.0f, 2, 2);
    k_qrelu<<<(NELEM/4 + 255)/256, 256>>>();

    k_conv<2><<<cg, 256, SMEM_CONV>>>();
    k_final<<<dim3(HWsz/32, C/32, NB), 256>>>(out);
}

// round 14
// speedup vs baseline: 2.2515x; 1.1763x over previous
#include <cuda_runtime.h>
#include <cstdint>

#define NB 32
#define C  128
#define H  56
#define W  56
#define HWsz (H*W)
#define NPIX (NB*H*W)          /* 100352 */
#define NELEM (NPIX*C)         /* 12845056 */
#define WELEM (C*C*9)          /* 147456 */
#define XPART 1024

// -------- scratch (device globals; no allocations) --------
__device__ __align__(16) int8_t g_x_i8[NELEM];   // quantized input, NHWC, [-8,7]
__device__ __align__(16) int8_t g_a1[NELEM];     // quantized relu1 acts, NHWC, [0,15]
__device__ __align__(16) int8_t g_w1q[WELEM];    // [co][kh][kw][ci]
__device__ __align__(16) int8_t g_w2q[WELEM];
__device__ __align__(16) float  g_t[NELEM];      // conv outputs, NHWC (both passes)
__device__ float g_part[XPART + 128];            // absmax partials: x[1024], w1[64], w2[64]
__device__ unsigned g_max[8];                    // 0:|x| 1:|w1| 2:|w2| 3:relu1 4:relu2
__device__ float g_A1[C], g_D1[C], g_A2[C], g_D2[C];

// -------- launch 0: per-block abs-max partials (plain stores, no init needed) --------
__global__ void __launch_bounds__(256) k_absmax_part(const float* __restrict__ x,
                                                     const float* __restrict__ w1,
                                                     const float* __restrict__ w2) {
    int bid = blockIdx.x;
    float m = 0.f;
    if (bid < XPART) {
        for (int i = bid*256 + threadIdx.x; i < NELEM; i += XPART*256)
            m = fmaxf(m, fabsf(x[i]));
    } else if (bid < XPART + 64) {
        int b = bid - XPART;
        for (int i = b*256 + threadIdx.x; i < WELEM; i += 64*256)
            m = fmaxf(m, fabsf(w1[i]));
    } else {
        int b = bid - XPART - 64;
        for (int i = b*256 + threadIdx.x; i < WELEM; i += 64*256)
            m = fmaxf(m, fabsf(w2[i]));
    }
    #pragma unroll
    for (int off = 16; off; off >>= 1) m = fmaxf(m, __shfl_xor_sync(0xffffffffu, m, off));
    __shared__ float sm[8];
    int lane = threadIdx.x & 31, wid = threadIdx.x >> 5;
    if (lane == 0) sm[wid] = m;
    __syncthreads();
    if (threadIdx.x == 0) {
        float mm = sm[0];
        #pragma unroll
        for (int i = 1; i < 8; i++) mm = fmaxf(mm, sm[i]);
        g_part[bid] = mm;
    }
}

__device__ __forceinline__ float blockmax256(float m, float* sm) {
    #pragma unroll
    for (int off = 16; off; off >>= 1) m = fmaxf(m, __shfl_xor_sync(0xffffffffu, m, off));
    int lane = threadIdx.x & 31, wid = threadIdx.x >> 5;
    if (lane == 0) sm[wid] = m;
    __syncthreads();
    float r = sm[0];
    #pragma unroll
    for (int i = 1; i < 8; i++) r = fmaxf(r, sm[i]);
    __syncthreads();
    return r;
}

// -------- launch 1: reduce partials -> g_max[0..2]; zero relu slots; affine1 --------
__global__ void __launch_bounds__(256) k_prep(const float* __restrict__ b1,
                                              const float* __restrict__ g1,
                                              const float* __restrict__ be1,
                                              const float* __restrict__ m1,
                                              const float* __restrict__ v1) {
    __shared__ float sm[8];
    int tid = threadIdx.x;
    float m = 0.f;
    for (int i = tid; i < XPART; i += 256) m = fmaxf(m, g_part[i]);
    float s0 = blockmax256(m, sm);
    float s1 = blockmax256((tid < 64) ? g_part[XPART + tid] : 0.f, sm);
    float s2 = blockmax256((tid < 64) ? g_part[XPART + 64 + tid] : 0.f, sm);
    if (tid == 0) {
        g_max[0] = __float_as_uint(s0);
        g_max[1] = __float_as_uint(s1);
        g_max[2] = __float_as_uint(s2);
        g_max[3] = 0u;
        g_max[4] = 0u;
    }
    if (tid < C) {
        float si = fmaxf(s0 / 7.0f, 1e-8f);
        float sw = fmaxf(s1 / 7.0f, 1e-8f);
        float sb = si * sw;
        float qb = rintf(b1[tid] / sb);
        float inv = g1[tid] / sqrtf(v1[tid] + 1e-5f);
        g_A1[tid] = sb * inv;
        g_D1[tid] = qb * sb * inv + be1[tid] - m1[tid] * inv;
    }
}

// -------- launch 2: fused quantize (x -> NHWC int8, w1/w2 -> [co][tap][ci] int8) ----
__global__ void __launch_bounds__(256) k_quant_all(const float* __restrict__ x,
                                                   const float* __restrict__ wA,
                                                   const float* __restrict__ wB) {
    __shared__ int8_t tile[32 * 144];
    int bid = blockIdx.x;
    if (bid < 3136) {
        int n = bid / 98, hw0 = (bid % 98) * 32;
        float s = fmaxf(__uint_as_float(g_max[0]) / 7.0f, 1e-8f);
        int lane = threadIdx.x & 31, ty = threadIdx.x >> 5;
        #pragma unroll
        for (int it = 0; it < 16; it++) {
            int c = ty + 8 * it;
            float v = x[((size_t)n*C + c)*HWsz + hw0 + lane];
            tile[lane * 144 + c] = (int8_t)fminf(fmaxf(rintf(v/s), -8.f), 7.f);
        }
        __syncthreads();
        int p = threadIdx.x >> 3, w16 = threadIdx.x & 7;
        int4 v = *(const int4*)(tile + p * 144 + w16 * 16);
        *(int4*)(g_x_i8 + (size_t)(n*HWsz + hw0 + p)*C + w16*16) = v;
    } else {
        int gi = (bid - 3136)*256 + threadIdx.x;       // 1152 blocks * 256 = 2*WELEM exactly
        int which = gi >= WELEM;
        int i = which ? (gi - WELEM) : gi;
        const float* w = which ? wB : wA;
        float s = fmaxf(__uint_as_float(g_max[which ? 2 : 1]) / 7.0f, 1e-8f);
        int ci = i & (C-1);
        int kw = (i >> 7) % 3;
        int kh = ((i >> 7) / 3) % 3;
        int co = i / (9*C);
        float v = w[((size_t)(co*C + ci)*3 + kh)*3 + kw];
        signed char q = (signed char)fminf(fmaxf(rintf(v/s), -8.f), 7.f);
        if (which) g_w2q[i] = q; else g_w1q[i] = q;
    }
}

// -------- affine2 (needs relu1 max) --------
__global__ void k_affine(const float* __restrict__ b, const float* __restrict__ g,
                         const float* __restrict__ be, const float* __restrict__ m,
                         const float* __restrict__ v,
                         int slot_in, float div_in, int slot_w, int which) {
    int c = threadIdx.x;
    if (c >= C) return;
    float si = fmaxf(__uint_as_float(g_max[slot_in]) / div_in, 1e-8f);
    float sw = fmaxf(__uint_as_float(g_max[slot_w]) / 7.0f, 1e-8f);
    float sb = si * sw;
    float qb = rintf(b[c] / sb);
    float inv = g[c] / sqrtf(v[c] + 1e-5f);
    float A  = sb * inv;
    float Dv = qb * sb * inv + be[c] - m[c] * inv;
    if (which == 1) { g_A1[c] = A; g_D1[c] = Dv; }
    else            { g_A2[c] = A; g_D2[c] = Dv; }
}

// ================= int8 tensor-core conv (mma.sync m16n8k32) =================
// Block = 2 image rows (112 px -> M=128) x 64 couts (half = blockIdx.y).
// 101 KB smem -> 2 blocks/SM = 16 warps/SM (vs 8 before) for latency hiding.
// SMEM XOR-swizzled: chunk c within 128B row stored at c ^ (row&7) (conflict-free LDSM).

#define SW2_BYTES (9*C*64)        /* 73728 */
#define SA_BYTES (4*58*C)         /* 29696 */
#define SMEM_CONV (SW2_BYTES + SA_BYTES)   /* 103424 */

__device__ __forceinline__ uint32_t s2u(const void* p) {
    return (uint32_t)__cvta_generic_to_shared(p);
}
#define LDSM4(r0,r1,r2,r3,addr) \
    asm volatile("ldmatrix.sync.aligned.m8n8.x4.shared.b16 {%0,%1,%2,%3}, [%4];" \
        : "=r"(r0),"=r"(r1),"=r"(r2),"=r"(r3) : "r"(addr))
#define MMA16832(c,a0,a1,a2,a3,b0,b1) \
    asm volatile("mma.sync.aligned.m16n8k32.row.col.s32.s8.s8.s32 " \
        "{%0,%1,%2,%3},{%4,%5,%6,%7},{%8,%9},{%0,%1,%2,%3};" \
        : "+r"((c)[0]),"+r"((c)[1]),"+r"((c)[2]),"+r"((c)[3]) \
        : "r"(a0),"r"(a1),"r"(a2),"r"(a3),"r"(b0),"r"(b1))

template<int PASS>
__global__ void __launch_bounds__(256, 2) k_conv() {
    extern __shared__ __align__(16) int8_t smc[];
    int8_t* sw = smc;                 // weights [64 co][tap][ci], swizzled
    int8_t* sa = smc + SW2_BYTES;     // act slab [4 rows][58 cols][128 ci], swizzled
    const int8_t* __restrict__ in = (PASS == 1) ? g_x_i8 : g_a1;
    const int8_t* __restrict__ wq = (PASS == 1) ? g_w1q  : g_w2q;
    const float*  __restrict__ Ap = (PASS == 1) ? g_A1 : g_A2;
    const float*  __restrict__ Dp = (PASS == 1) ? g_D1 : g_D2;

    int n = blockIdx.z, half = blockIdx.y, h2 = blockIdx.x;   // output rows 2*h2, 2*h2+1
    int tid = threadIdx.x;

    // fill 64-cout weight half (coalesced read; dest chunk swizzled by co_local&7)
    {
        const int4* src = (const int4*)wq + (size_t)half * 64 * 72;
        int4* dst = (int4*)sw;
        #pragma unroll 4
        for (int i = tid; i < SW2_BYTES/16; i += 256) {
            int col = i / 72;                      // co_local
            dst[(i & ~7) | ((i ^ col) & 7)] = src[i];
        }
    }
    // fill act slab (dest chunk swizzled by slab-pixel-row &7)
    {
        int4* dst = (int4*)sa;
        for (int i = tid; i < SA_BYTES/16; i += 256) {
            int rowi = i >> 3;                  // slab pixel index 0..231
            int ir = rowi / 58, col = rowi % 58;
            int hh = h2*2 + ir - 1, ww = col - 1;
            int4 v = make_int4(0,0,0,0);
            if ((unsigned)hh < (unsigned)H && (unsigned)ww < (unsigned)W)
                v = __ldg((const int4*)(in + (size_t)((n*H + hh)*W + ww)*C) + (i & 7));
            dst[(i & ~7) | ((i ^ rowi) & 7)] = v;
        }
    }
    __syncthreads();

    int warp = tid >> 5, L = tid & 31;

    // A fragment lane geometry (16 px per warp, 8 warps -> 128 M rows incl dummies)
    int apix = warp*16 + (L & 15);
    int ph = apix / 56, pw = apix % 56;
    if (apix >= 112) { ph = 0; pw = 0; }        // dummy rows, results discarded
    int sBase = ph*58 + pw;
    int hk = L >> 4;
    uint32_t saU = s2u(sa);

    // B fragment lane geometry: co_local = (L&7) + 8*(L>>4), g loop covers 4x16 couts
    int coL = (L & 7) + ((L >> 4) << 3);
    int hkb = (L >> 3) & 1;
    int sxb = L & 7;
    uint32_t bRow = s2u(sw) + (uint32_t)(coL * (9*C));

    int acc[8][4];
    #pragma unroll
    for (int t = 0; t < 8; t++) { acc[t][0]=0; acc[t][1]=0; acc[t][2]=0; acc[t][3]=0; }

    for (int tap = 0; tap < 9; tap++) {
        int kh = tap / 3, kw = tap - 3*kh;
        int s = sBase + kh*58 + kw;
        uint32_t aRow = saU + (uint32_t)(s * C);
        int sx = s & 7;
        uint32_t bT = bRow + (uint32_t)(tap*C);
        #pragma unroll
        for (int ks = 0; ks < 4; ks++) {
            uint32_t a0,a1,a2,a3;
            LDSM4(a0,a1,a2,a3, aRow + (uint32_t)(((2*ks + hk) ^ sx) << 4));
            uint32_t bOff = (uint32_t)(((2*ks + hkb) ^ sxb) << 4);
            #pragma unroll
            for (int g = 0; g < 4; g++) {
                uint32_t b0,b1,b2,b3;
                LDSM4(b0,b1,b2,b3, bT + (uint32_t)(g * 16 * (9*C)) + bOff);
                MMA16832(acc[2*g  ], a0,a1,a2,a3, b0,b1);
                MMA16832(acc[2*g+1], a0,a1,a2,a3, b2,b3);
            }
        }
    }

    // epilogue: v = acc*A[co] + D[co] (+ residual), relu-max, NHWC float store
    float sid = 0.f;
    if (PASS == 2) sid = fmaxf(__uint_as_float(g_max[0]) / 7.0f, 1e-8f);
    int row0 = warp*16 + (L >> 2);
    int q2 = (L & 3) * 2;
    float lmax = 0.f;
    #pragma unroll
    for (int t = 0; t < 8; t++) {
        int co = half*64 + t*8 + q2;
        float A0 = Ap[co], A1 = Ap[co+1], D0 = Dp[co], D1 = Dp[co+1];
        #pragma unroll
        for (int hf = 0; hf < 2; hf++) {
            int pix = row0 + 8*hf;
            if (pix < 112) {
                int gp = (n*H + h2*2 + pix/56)*W + pix%56;
                float v0 = (float)acc[t][2*hf  ] * A0 + D0;
                float v1 = (float)acc[t][2*hf+1] * A1 + D1;
                if (PASS == 2) {
                    char2 rr = *(const char2*)&g_x_i8[(size_t)gp*C + co];
                    v0 += sid * (float)rr.x;
                    v1 += sid * (float)rr.y;
                }
                lmax = fmaxf(lmax, fmaxf(v0, v1));
                float2 o; o.x = v0; o.y = v1;
                *(float2*)&g_t[(size_t)gp*C + co] = o;
            }
        }
    }

    #pragma unroll
    for (int off = 16; off; off >>= 1) lmax = fmaxf(lmax, __shfl_xor_sync(0xffffffffu, lmax, off));
    __shared__ float smax[8];
    if (L == 0) smax[warp] = lmax;
    __syncthreads();
    if (tid == 0) {
        float mm = smax[0];
        #pragma unroll
        for (int i = 1; i < 8; i++) mm = fmaxf(mm, smax[i]);
        atomicMax(&g_max[(PASS == 1) ? 3 : 4], __float_as_uint(mm));
    }
}

// -------- QuantReLU of conv1 output -> uint4-as-int8 NHWC --------
__global__ void k_qrelu() {
    int i = blockIdx.x*blockDim.x + threadIdx.x;
    if (i >= NELEM/4) return;
    float s = fmaxf(__uint_as_float(g_max[3]) / 15.0f, 1e-8f);
    float4 v = ((const float4*)g_t)[i];
    char4 q;
    q.x = (signed char)fminf(fmaxf(rintf(fmaxf(v.x, 0.f)/s), 0.f), 15.f);
    q.y = (signed char)fminf(fmaxf(rintf(fmaxf(v.y, 0.f)/s), 0.f), 15.f);
    q.z = (signed char)fminf(fmaxf(rintf(fmaxf(v.z, 0.f)/s), 0.f), 15.f);
    q.w = (signed char)fminf(fmaxf(rintf(fmaxf(v.w, 0.f)/s), 0.f), 15.f);
    ((char4*)g_a1)[i] = q;
}

// -------- final QuantReLU + NHWC->NCHW transpose, smem-tiled --------
__global__ void __launch_bounds__(256) k_final(float* __restrict__ out) {
    __shared__ float tile[32][33];
    int n = blockIdx.z, c0 = blockIdx.y * 32, hw0 = blockIdx.x * 32;
    float s = fmaxf(__uint_as_float(g_max[4]) / 15.0f, 1e-8f);
    int lane = threadIdx.x & 31, ty = threadIdx.x >> 5;
    #pragma unroll
    for (int it = 0; it < 4; it++) {
        int p = ty + 8 * it;
        float v = g_t[(size_t)(n*HWsz + hw0 + p)*C + c0 + lane];
        tile[lane][p] = fminf(fmaxf(rintf(fmaxf(v, 0.f)/s), 0.f), 15.f) * s;
    }
    __syncthreads();
    #pragma unroll
    for (int it = 0; it < 4; it++) {
        int c = ty + 8 * it;
        out[((size_t)n*C + c0 + c)*HWsz + hw0 + lane] = tile[c][lane];
    }
}

extern "C" void kernel_launch(void* const* d_in, const int* in_sizes, int n_in,
                              void* d_out, int out_size) {
    const float* x   = (const float*)d_in[0];
    const float* w1  = (const float*)d_in[1];
    const float* b1  = (const float*)d_in[2];
    const float* g1  = (const float*)d_in[3];
    const float* be1 = (const float*)d_in[4];
    const float* m1  = (const float*)d_in[5];
    const float* v1  = (const float*)d_in[6];
    const float* w2  = (const float*)d_in[7];
    const float* b2  = (const float*)d_in[8];
    const float* g2  = (const float*)d_in[9];
    const float* be2 = (const float*)d_in[10];
    const float* m2  = (const float*)d_in[11];
    const float* v2  = (const float*)d_in[12];
    float* out = (float*)d_out;

    cudaFuncSetAttribute(k_conv<1>, cudaFuncAttributeMaxDynamicSharedMemorySize, SMEM_CONV);
    cudaFuncSetAttribute(k_conv<2>, cudaFuncAttributeMaxDynamicSharedMemorySize, SMEM_CONV);

    dim3 cg(H/2, 2, NB);   // 28 x 2 x 32 = 1792 blocks, 2/SM

    k_absmax_part<<<XPART + 128, 256>>>(x, w1, w2);       // 0
    k_prep<<<1, 256>>>(b1, g1, be1, m1, v1);              // 1
    k_quant_all<<<3136 + 1152, 256>>>(x, w1, w2);         // 2
    k_conv<1><<<cg, 256, SMEM_CONV>>>();                  // 3  <- ncu lands here
    k_affine<<<1, 128>>>(b2, g2, be2, m2, v2, 3, 15.0f, 2, 2);  // 4
    k_qrelu<<<(NELEM/4 + 255)/256, 256>>>();              // 5
    k_conv<2><<<cg, 256, SMEM_CONV>>>();                  // 6
    k_final<<<dim3(HWsz/32, C/32, NB), 256>>>(out);       // 7
}